// round 7
// baseline (speedup 1.0000x reference)
#include <cuda_runtime.h>

// out[b,c,h,w] = x[b,c,h,w] * (h%3 != 0) * (w%3 != 0)
//
// Unfold(k=2, stride=3, dil=2, pad=1) + fold with identical geometry reduces to
// an elementwise 0/1 coverage mask, separable in h and w. Rows with h%3==0 are
// all-zero in the output; their input lines are never read (predicated LDG).
// Mandatory traffic: 88 MB read + 134 MB write = 222 MB; measured combined
// memory-path ceiling ~7.2 TB/s => floor ~30.8 us (kernel time).
//
// R7: persistent single-wave kernel (148 SMs x 4 CTAs x 256 thr) with a
// grid-stride loop, 4 batched predicated loads per iteration. Thread-count
// stride = 151,552 float4 = 592 whole 32x32 planes, so all 4 accesses in an
// iteration share one (h,w) mask. Removes wave-transition + tail overheads.

static constexpr int THREADS = 256;
static constexpr int BLOCKS  = 148 * 4;            // one full wave
static constexpr int TSTRIDE = THREADS * BLOCKS;   // 151,552 (592 planes)

__global__ void __launch_bounds__(THREADS)
unfoldfold_mask_kernel(const float4* __restrict__ x,
                       float4* __restrict__ out,
                       int n4) {
    int tid = blockIdx.x * THREADS + threadIdx.x;

    for (int j0 = tid; j0 < n4; j0 += 4 * TSTRIDE) {
        // Mask depends only on j0 mod 256 (one plane = 256 float4); the three
        // strided partners share it because TSTRIDE is plane-aligned.
        int e  = j0 << 2;
        int w0 = e & 31;
        int h  = (e >> 5) & 31;

        bool  ldp = (h % 3 != 0);
        float hm  = ldp ? 1.0f : 0.0f;
        float m0 = hm * (float)(((w0 + 0) % 3) != 0);
        float m1 = hm * (float)(((w0 + 1) % 3) != 0);
        float m2 = hm * (float)(((w0 + 2) % 3) != 0);
        float m3 = hm * (float)(((w0 + 3) % 3) != 0);

        int j1 = j0 + TSTRIDE;
        int j2 = j0 + 2 * TSTRIDE;
        int j3 = j0 + 3 * TSTRIDE;

        bool b1 = j1 < n4, b2 = j2 < n4, b3 = j3 < n4;

        float4 z = make_float4(0.f, 0.f, 0.f, 0.f);
        float4 v0 = z, v1 = z, v2 = z, v3 = z;

        // Single-load bodies -> predicated LDG.128, batched (MLP = 4).
        if (ldp)       v0 = x[j0];
        if (ldp && b1) v1 = x[j1];
        if (ldp && b2) v2 = x[j2];
        if (ldp && b3) v3 = x[j3];

        v0.x *= m0; v0.y *= m1; v0.z *= m2; v0.w *= m3;
        v1.x *= m0; v1.y *= m1; v1.z *= m2; v1.w *= m3;
        v2.x *= m0; v2.y *= m1; v2.z *= m2; v2.w *= m3;
        v3.x *= m0; v3.y *= m1; v3.z *= m2; v3.w *= m3;

        out[j0] = v0;
        if (b1) out[j1] = v1;
        if (b2) out[j2] = v2;
        if (b3) out[j3] = v3;
    }
}

extern "C" void kernel_launch(void* const* d_in, const int* in_sizes, int n_in,
                              void* d_out, int out_size) {
    const float4* x = (const float4*)d_in[0];
    float4* out     = (float4*)d_out;

    int n  = in_sizes[0];      // 64*512*32*32 = 33,554,432
    int n4 = n >> 2;           // 8,388,608 float4s

    unfoldfold_mask_kernel<<<BLOCKS, THREADS>>>(x, out, n4);
}

// round 8
// speedup vs baseline: 1.1097x; 1.1097x over previous
#include <cuda_runtime.h>

// out[b,c,h,w] = x[b,c,h,w] * (h%3 != 0) * (w%3 != 0)
//
// Unfold(k=2,stride=3,dil=2,pad=1)+fold(identical geometry) == elementwise 0/1
// coverage mask, separable in h,w. Rows h%3==0 are all-zero in the output.
//
// R8: split the grid into two specialized block ranges:
//  - LIVE blocks: rows h%3!=0. Unconditional LDG.128 (no predicates), 4
//    plane-strided loads batched per thread (MLP=4), masked multiply, store.
//  - ZERO blocks: rows h%3==0. Pure stores of zero — no loads, no scoreboard
//    waits, so they drain write bandwidth immediately and decouple the write
//    stream from read latency.
//
// Geometry: 32768 planes of 32x32 f32; one plane = 256 float4; one row = 8
// float4 (one 128B line). Live rows per plane: 21 (h = 3k/2 + 1, k=0..20).
// Zero rows per plane: 11 (h = 3k, k=0..10).

static constexpr int THREADS     = 256;
static constexpr int PLANES      = 64 * 512;                    // 32768
static constexpr int PQ          = PLANES / 4;                  // 8192 (plane chunk)
static constexpr int LIVE_F4     = PQ * 21 * 8;                 // 1,376,256 per chunk
static constexpr int ZERO_F4     = PLANES * 11 * 8;             // 2,883,584
static constexpr int LIVE_BLOCKS = LIVE_F4 / THREADS;           // 5376
static constexpr int ZERO_BLOCKS = ZERO_F4 / THREADS;           // 11264

__global__ void __launch_bounds__(THREADS)
unfoldfold_split_kernel(const float4* __restrict__ x,
                        float4* __restrict__ out) {
    int b = blockIdx.x;

    if (b < LIVE_BLOCKS) {
        // ---- live rows: read, mask by w, write ----
        int t = b * THREADS + threadIdx.x;      // [0, LIVE_F4)
        int c  = t & 7;                          // float4 column within row
        int r  = t >> 3;                         // live-row serial
        int k  = r % 21;                         // live-row index within plane
        int p0 = r / 21;                         // plane within first chunk
        int h  = (3 * k) / 2 + 1;                // 1,2,4,5,7,8,...,31

        int w0 = c << 2;
        float m0 = (float)(((w0 + 0) % 3) != 0);
        float m1 = (float)(((w0 + 1) % 3) != 0);
        float m2 = (float)(((w0 + 2) % 3) != 0);
        float m3 = (float)(((w0 + 3) % 3) != 0);

        int base = h * 8 + c;                    // offset within a plane
        int i0 = (p0         ) * 256 + base;
        int i1 = (p0 +     PQ) * 256 + base;
        int i2 = (p0 + 2 * PQ) * 256 + base;
        int i3 = (p0 + 3 * PQ) * 256 + base;

        // Unconditional, batched loads (MLP = 4)
        float4 v0 = x[i0];
        float4 v1 = x[i1];
        float4 v2 = x[i2];
        float4 v3 = x[i3];

        v0.x *= m0; v0.y *= m1; v0.z *= m2; v0.w *= m3;
        v1.x *= m0; v1.y *= m1; v1.z *= m2; v1.w *= m3;
        v2.x *= m0; v2.y *= m1; v2.z *= m2; v2.w *= m3;
        v3.x *= m0; v3.y *= m1; v3.z *= m2; v3.w *= m3;

        out[i0] = v0;
        out[i1] = v1;
        out[i2] = v2;
        out[i3] = v3;
    } else {
        // ---- zero rows: pure stores, no loads, no waits ----
        int t = (b - LIVE_BLOCKS) * THREADS + threadIdx.x;   // [0, ZERO_F4)
        int c = t & 7;
        int r = t >> 3;
        int k = r % 11;                          // zero-row index within plane
        int p = r / 11;
        int h = 3 * k;                           // 0,3,...,30

        out[p * 256 + h * 8 + c] = make_float4(0.f, 0.f, 0.f, 0.f);
    }
}

extern "C" void kernel_launch(void* const* d_in, const int* in_sizes, int n_in,
                              void* d_out, int out_size) {
    const float4* x = (const float4*)d_in[0];
    float4* out     = (float4*)d_out;

    unfoldfold_split_kernel<<<LIVE_BLOCKS + ZERO_BLOCKS, THREADS>>>(x, out);
}